// round 6
// baseline (speedup 1.0000x reference)
#include <cuda_runtime.h>

#define Hc 2048
#define Wc 2048
#define UH 2049
#define UW 2048
#define VH 2048
#define VW 2049
#define DT 0.01f
#define VISC 0.001f

// Device scratch
__device__ float g_u  [UH * UW];
__device__ float g_v  [VH * VW];
__device__ float g_u2 [UH * UW];
__device__ float g_v2 [VH * VW];
__device__ float g_dens[Hc * Wc];
__device__ float g_div [Hc * Wc];
__device__ float g_p  [Hc * Wc];
__device__ float g_p2 [Hc * Wc];

__device__ __forceinline__ float bilerp(const float* __restrict__ f, int h, int w,
                                        float y, float x) {
    int x0 = (int)floorf(x);
    int x1 = x0 + 1;
    int y0 = (int)floorf(y);
    int y1 = y0 + 1;
    x0 = min(max(x0, 0), w - 1);
    x1 = min(max(x1, 0), w - 1);
    y0 = min(max(y0, 0), h - 1);
    y1 = min(max(y1, 0), h - 1);
    float x0f = (float)x0, x1f = (float)x1;
    float y0f = (float)y0, y1f = (float)y1;
    float wa = (x1f - x) * (y1f - y);
    float wb = (x - x0f) * (y1f - y);
    float wc = (x1f - x) * (y - y0f);
    float wd = (x - x0f) * (y - y0f);
    return wa * f[y0 * w + x0] + wb * f[y0 * w + x1]
         + wc * f[y1 * w + x0] + wd * f[y1 * w + x1];
}

// ---- diffuse, float4, 2 rows per thread ----
__global__ void diffuse_f4x2_kernel(const float* __restrict__ f, float* __restrict__ out,
                                    int h, int w, float a) {
    int qx = blockIdx.x * blockDim.x + threadIdx.x;
    int ip = blockIdx.y * blockDim.y + threadIdx.y;
    int w4 = w >> 2;
    int r0 = ip * 2;
    if (r0 >= h || qx >= w4) return;
    int r1 = r0 + 1;
    bool has1 = (r1 < h);
    int j0 = qx * 4;
    const float4* f4 = (const float4*)f;

    float4 A = f4[max(r0 - 1, 0) * w4 + qx];        // row r0-1
    float4 B = f4[r0 * w4 + qx];                    // row r0
    float4 C = has1 ? f4[r1 * w4 + qx] : B;         // row r1
    float4 D = f4[min(r1 + 1, h - 1) * w4 + qx];    // row r1+1 (or clamp)
    float4 dn0 = has1 ? C : B;                      // below r0 (clamped if r0 last)

    float lf0 = (j0 > 0)     ? f[r0 * w + j0 - 1] : B.x;
    float rt0 = (j0 + 4 < w) ? f[r0 * w + j0 + 4] : B.w;
    float4 o0;
    o0.x = B.x + a * (A.x + dn0.x + lf0 + B.y - 4.0f * B.x);
    o0.y = B.y + a * (A.y + dn0.y + B.x + B.z - 4.0f * B.y);
    o0.z = B.z + a * (A.z + dn0.z + B.y + B.w - 4.0f * B.z);
    o0.w = B.w + a * (A.w + dn0.w + B.z + rt0  - 4.0f * B.w);
    ((float4*)out)[r0 * w4 + qx] = o0;

    if (has1) {
        float lf1 = (j0 > 0)     ? f[r1 * w + j0 - 1] : C.x;
        float rt1 = (j0 + 4 < w) ? f[r1 * w + j0 + 4] : C.w;
        float4 o1;
        o1.x = C.x + a * (B.x + D.x + lf1 + C.y - 4.0f * C.x);
        o1.y = C.y + a * (B.y + D.y + C.x + C.z - 4.0f * C.y);
        o1.z = C.z + a * (B.z + D.z + C.y + C.w - 4.0f * C.z);
        o1.w = C.w + a * (B.w + D.w + C.z + rt1  - 4.0f * C.w);
        ((float4*)out)[r1 * w4 + qx] = o1;
    }
}

// ---- diffuse v with force (scalar; VW=2049 unaligned) ----
__device__ __forceinline__ float vforce(const float* __restrict__ v,
                                        const float* __restrict__ dens,
                                        int i, int j) {
    float val = v[i * VW + j];
    if (j < Wc) val += (DT * 0.1f) * dens[i * Wc + j];
    return val;
}

__global__ void diffuse_v_force_kernel(const float* __restrict__ v,
                                       const float* __restrict__ dens,
                                       float* __restrict__ out, float a) {
    int j = blockIdx.x * blockDim.x + threadIdx.x;
    int i = blockIdx.y * blockDim.y + threadIdx.y;
    if (i >= VH || j >= VW) return;
    float c  = vforce(v, dens, i, j);
    float up = vforce(v, dens, max(i - 1, 0), j);
    float dn = vforce(v, dens, min(i + 1, VH - 1), j);
    float lf = vforce(v, dens, i, max(j - 1, 0));
    float rt = vforce(v, dens, i, min(j + 1, VW - 1));
    out[i * VW + j] = c + a * (up + dn + lf + rt - 4.0f * c);
}

// ---- divergence ----
__global__ void div_f4_kernel(const float* __restrict__ u, const float* __restrict__ v,
                              float* __restrict__ dv) {
    int qx = blockIdx.x * blockDim.x + threadIdx.x;
    int i  = blockIdx.y * blockDim.y + threadIdx.y;
    int w4 = Wc >> 2;
    if (i >= Hc || qx >= w4) return;
    int j0 = qx * 4;
    const float4* u4 = (const float4*)u;
    float4 u0 = u4[i * w4 + qx];
    float4 u1 = u4[(i + 1) * w4 + qx];
    const float* vr = v + i * VW + j0;
    float v0 = vr[0], v1 = vr[1], v2 = vr[2], v3 = vr[3], v4 = vr[4];
    float4 r;
    r.x = (u1.x - u0.x + v1 - v0) / DT;
    r.y = (u1.y - u0.y + v2 - v1) / DT;
    r.z = (u1.z - u0.z + v3 - v2) / DT;
    r.w = (u1.w - u0.w + v4 - v3) / DT;
    ((float4*)dv)[i * w4 + qx] = r;
}

// ============ fused Jacobi: horizontal 16-col strips, no shfl ============
// Block (4,64): thread = 1 row x 16 cols. Tile 64x64, halo HALO, output
// (64-2*HALO)^2. div in registers; p tile ping-held in smem (single buffer:
// read rows ty-1/ty/ty+1, sync, write row ty, sync).
#define JSTRIDE 68

__device__ __forceinline__ float gload(const float* __restrict__ p, int gy, int gx) {
    return (gy >= 0 && gy < Hc && gx >= 0 && gx < Wc) ? p[gy * Wc + gx] : 0.0f;
}

template<int HALO, int JT>
__global__ void __launch_bounds__(256)
jacobiS_kernel(const float* __restrict__ pin, const float* __restrict__ dv,
               float* __restrict__ pout, int p_zero) {
    __shared__ float sT[64 * JSTRIDE];

    const int OTl = 64 - 2 * HALO;
    const int tx = threadIdx.x;     // 0..3  (16-col strip)
    const int ty = threadIdx.y;     // 0..63 (row)
    const int bx0 = blockIdx.x * OTl - HALO;
    const int by0 = blockIdx.y * OTl - HALO;
    const int gy  = by0 + ty;
    const int c0  = tx * 16;        // tile col of strip start
    const int gx0 = bx0 + c0;
    const bool border = (bx0 < 0 || by0 < 0 || bx0 + 64 > Wc || by0 + 64 > Hc);

    float4 d[4];
    float4 o[4];

    // ---- load div (registers) and p (into smem) ----
    if (!border) {
        const float4* dv4 = (const float4*)dv;
        int base = (gy * Wc + gx0) >> 2;
        #pragma unroll
        for (int m = 0; m < 4; m++) d[m] = dv4[base + m];
        if (p_zero) {
            float4 z = make_float4(0.f, 0.f, 0.f, 0.f);
            #pragma unroll
            for (int m = 0; m < 4; m++) o[m] = z;
        } else {
            const float4* p4 = (const float4*)pin;
            #pragma unroll
            for (int m = 0; m < 4; m++) o[m] = p4[base + m];
        }
    } else {
        #pragma unroll
        for (int m = 0; m < 4; m++) {
            int gx = gx0 + m * 4;
            d[m] = make_float4(gload(dv, gy, gx),     gload(dv, gy, gx + 1),
                               gload(dv, gy, gx + 2), gload(dv, gy, gx + 3));
            if (p_zero) o[m] = make_float4(0.f, 0.f, 0.f, 0.f);
            else        o[m] = make_float4(gload(pin, gy, gx),     gload(pin, gy, gx + 1),
                                           gload(pin, gy, gx + 2), gload(pin, gy, gx + 3));
        }
    }
    #pragma unroll
    for (int m = 0; m < 4; m++)
        *(float4*)&sT[ty * JSTRIDE + c0 + m * 4] = o[m];
    __syncthreads();

    // domain-interior masks (used only by border blocks)
    const bool rok = (gy >= 1 && gy <= Hc - 2);
    bool ok[16];
    #pragma unroll
    for (int e = 0; e < 16; e++) {
        int gx = gx0 + e;
        ok[e] = rok && (gx >= 1 && gx <= Wc - 2);
    }

    const bool rowActive = (ty >= 1 && ty <= 62);
    const int lfIdx = (c0 == 0)  ? 0  : c0 - 1;    // clamped (garbage-safe, finite)
    const int rtIdx = (c0 == 48) ? 63 : c0 + 16;

    #pragma unroll
    for (int t = 0; t < JT; t++) {
        if (rowActive) {
            const float* rup = &sT[(ty - 1) * JSTRIDE];
            const float* rdn = &sT[(ty + 1) * JSTRIDE];
            const float* rce = &sT[ty * JSTRIDE];
            float4 up[4], dn[4], ce[4];
            #pragma unroll
            for (int m = 0; m < 4; m++) {
                up[m] = *(const float4*)&rup[c0 + m * 4];
                dn[m] = *(const float4*)&rdn[c0 + m * 4];
                ce[m] = *(const float4*)&rce[c0 + m * 4];
            }
            float lf = rce[lfIdx];
            float rt = rce[rtIdx];
            #pragma unroll
            for (int m = 0; m < 4; m++) {
                float left  = (m == 0) ? lf : ce[m - 1].w;
                float right = (m == 3) ? rt : ce[m + 1].x;
                o[m].x = 0.25f * (up[m].x + dn[m].x + left    + ce[m].y - d[m].x);
                o[m].y = 0.25f * (up[m].y + dn[m].y + ce[m].x + ce[m].z - d[m].y);
                o[m].z = 0.25f * (up[m].z + dn[m].z + ce[m].y + ce[m].w - d[m].z);
                o[m].w = 0.25f * (up[m].w + dn[m].w + ce[m].z + right   - d[m].w);
            }
            if (border) {
                #pragma unroll
                for (int m = 0; m < 4; m++) {
                    o[m].x = ok[m * 4 + 0] ? o[m].x : 0.f;
                    o[m].y = ok[m * 4 + 1] ? o[m].y : 0.f;
                    o[m].z = ok[m * 4 + 2] ? o[m].z : 0.f;
                    o[m].w = ok[m * 4 + 3] ? o[m].w : 0.f;
                }
            }
        }
        __syncthreads();
        if (rowActive) {
            #pragma unroll
            for (int m = 0; m < 4; m++)
                *(float4*)&sT[ty * JSTRIDE + c0 + m * 4] = o[m];
        }
        __syncthreads();
    }

    // ---- store central output (rows/cols [HALO, 64-HALO)) from registers ----
    if (ty >= HALO && ty < 64 - HALO && gy < Hc) {
        #pragma unroll
        for (int m = 0; m < 4; m++) {
            int c4 = c0 + m * 4;
            if (c4 >= HALO && c4 + 4 <= 64 - HALO) {
                int gx = gx0 + m * 4;
                if (gx + 4 <= Wc)
                    *(float4*)&pout[gy * Wc + gx] = o[m];
            }
        }
    }
}

// ---- pressure gradient ----
__global__ void grad_u_f4_kernel(float* __restrict__ u, const float* __restrict__ p) {
    int qx = blockIdx.x * blockDim.x + threadIdx.x;
    int i  = blockIdx.y * blockDim.y + threadIdx.y + 1;
    int w4 = Wc >> 2;
    if (i > UH - 2 || qx >= w4) return;
    const float4* p4 = (const float4*)p;
    float4 pc = p4[i * w4 + qx];
    float4 pm = p4[(i - 1) * w4 + qx];
    float4* u4 = (float4*)u;
    float4 uu = u4[i * w4 + qx];
    uu.x -= DT * (pc.x - pm.x);
    uu.y -= DT * (pc.y - pm.y);
    uu.z -= DT * (pc.z - pm.z);
    uu.w -= DT * (pc.w - pm.w);
    u4[i * w4 + qx] = uu;
}

__global__ void grad_v_kernel(float* __restrict__ v, const float* __restrict__ p) {
    int j = blockIdx.x * blockDim.x + threadIdx.x + 1;
    int i = blockIdx.y * blockDim.y + threadIdx.y;
    if (i >= VH || j > VW - 2) return;
    v[i * VW + j] -= DT * (p[i * Wc + j] - p[i * Wc + j - 1]);
}

// ---- advects ----
__global__ void advect_u_kernel(const float* __restrict__ u, const float* __restrict__ v,
                                float* __restrict__ out) {
    int j = blockIdx.x * blockDim.x + threadIdx.x;
    int i = blockIdx.y * blockDim.y + threadIdx.y;
    if (i >= UH || j >= UW) return;
    float Y = (float)i, X = (float)j;
    float x_u = fminf(fmaxf(X + 0.5f, 0.0f), (float)(UW - 1));
    float u_i = bilerp(u, UH, UW, Y, x_u);
    float y_v = fminf(fmaxf(Y + 0.5f, 0.0f), (float)(VH - 1));
    float v_i = bilerp(v, VH, VW, y_v, X);
    float px = fminf(fmaxf(X - DT * u_i, 0.0f), (float)(UW - 1));
    float py = fminf(fmaxf(Y - DT * v_i, 0.0f), (float)(UH - 1));
    out[i * UW + j] = bilerp(u, UH, UW, py, px);
}

__global__ void advect_v_kernel(const float* __restrict__ vold, const float* __restrict__ unew,
                                float* __restrict__ out) {
    int j = blockIdx.x * blockDim.x + threadIdx.x;
    int i = blockIdx.y * blockDim.y + threadIdx.y;
    if (i >= VH || j >= VW) return;
    float Y = (float)i, X = (float)j;
    float x_u = fminf(fmaxf(X + 0.5f, 0.0f), (float)(UW - 1));
    float u_i = bilerp(unew, UH, UW, Y, x_u);
    float y_v = fminf(fmaxf(Y + 0.5f, 0.0f), (float)(VH - 1));
    float v_i = bilerp(vold, VH, VW, y_v, X);
    float px = fminf(fmaxf(X - DT * u_i, 0.0f), (float)(VW - 1));
    float py = fminf(fmaxf(Y - DT * v_i, 0.0f), (float)(VH - 1));
    out[i * VW + j] = bilerp(vold, VH, VW, py, px);
}

__global__ void advect_dens_kernel(const float* __restrict__ dens,
                                   const float* __restrict__ unew,
                                   const float* __restrict__ vnew,
                                   float* __restrict__ out) {
    int j = blockIdx.x * blockDim.x + threadIdx.x;
    int i = blockIdx.y * blockDim.y + threadIdx.y;
    if (i >= Hc || j >= Wc) return;
    float Y = (float)i, X = (float)j;
    float x_u = fminf(fmaxf(X + 0.5f, 0.0f), (float)(UW - 1));
    float u_i = bilerp(unew, UH, UW, Y, x_u);
    float y_v = fminf(fmaxf(Y + 0.5f, 0.0f), (float)(VH - 1));
    float v_i = bilerp(vnew, VH, VW, y_v, X);
    float px = fminf(fmaxf(X - DT * u_i, 0.0f), (float)(Wc - 1));
    float py = fminf(fmaxf(Y - DT * v_i, 0.0f), (float)(Hc - 1));
    out[i * Wc + j] = 0.995f * bilerp(dens, Hc, Wc, py, px);
}

extern "C" void kernel_launch(void* const* d_in, const int* in_sizes, int n_in,
                              void* d_out, int out_size) {
    const float* u_in    = (const float*)d_in[0];
    const float* v_in    = (const float*)d_in[1];
    const float* dens_in = (const float*)d_in[2];
    float* out = (float*)d_out;

    float *du, *dv_, *du2, *dv2, *dd, *ddiv, *dp, *dp2;
    cudaGetSymbolAddress((void**)&du,   g_u);
    cudaGetSymbolAddress((void**)&dv_,  g_v);
    cudaGetSymbolAddress((void**)&du2,  g_u2);
    cudaGetSymbolAddress((void**)&dv2,  g_v2);
    cudaGetSymbolAddress((void**)&dd,   g_dens);
    cudaGetSymbolAddress((void**)&ddiv, g_div);
    cudaGetSymbolAddress((void**)&dp,   g_p);
    cudaGetSymbolAddress((void**)&dp2,  g_p2);

    int w4 = Wc >> 2;
    dim3 blkQ(64, 4);
    dim3 grdQ_S((w4 + 63) / 64, (Hc + 3) / 4);

    dim3 blkS(128, 2);
    dim3 grdV((VW + 127) / 128, (VH + 1) / 2);
    dim3 grdU((UW + 127) / 128, (UH + 1) / 2);
    dim3 grdS((Wc + 127) / 128, (Hc + 1) / 2);

    // 1. diffuse (2 rows/thread)
    {
        dim3 blkD(64, 2);
        int puh = (UH + 1) / 2, psh = Hc / 2;
        dim3 grdDU((w4 + 63) / 64, (puh + 1) / 2);
        dim3 grdDS((w4 + 63) / 64, (psh + 1) / 2);
        diffuse_f4x2_kernel<<<grdDU, blkD>>>(u_in, du, UH, UW, DT * VISC);
        diffuse_v_force_kernel<<<grdV, blkS>>>(v_in, dens_in, dv_, DT * VISC);
        diffuse_f4x2_kernel<<<grdDS, blkD>>>(dens_in, dd, Hc, Wc, DT * VISC * 0.1f);
    }

    // 2. divergence
    div_f4_kernel<<<grdQ_S, blkQ>>>(du, dv_, ddiv);

    // 3. 20 Jacobi iterations = 8 + 8 + 4 (no-shfl horizontal strips)
    {
        dim3 blkJ(4, 64);
        int g8 = (Hc + 47) / 48;   // 43
        int g4 = (Hc + 55) / 56;   // 37
        dim3 grdJ8(g8, g8), grdJ4(g4, g4);
        jacobiS_kernel<8, 8><<<grdJ8, blkJ>>>(dp2, ddiv, dp, 1);   // iters 1-8 (p0=0)
        jacobiS_kernel<8, 8><<<grdJ8, blkJ>>>(dp, ddiv, dp2, 0);   // 9-16
        jacobiS_kernel<4, 4><<<grdJ4, blkJ>>>(dp2, ddiv, dp, 0);   // 17-20 -> dp
    }

    // 4. projection
    {
        dim3 grdGU((w4 + 63) / 64, ((UH - 2) + 3) / 4);
        grad_u_f4_kernel<<<grdGU, blkQ>>>(du, dp);
        dim3 grdGV(((VW - 2) + 127) / 128, (VH + 1) / 2);
        grad_v_kernel<<<grdGV, blkS>>>(dv_, dp);
    }

    // 5. advect
    advect_u_kernel<<<grdU, blkS>>>(du, dv_, du2);
    advect_v_kernel<<<grdV, blkS>>>(dv_, du2, dv2);
    advect_dens_kernel<<<grdS, blkS>>>(dd, du2, dv2, out);
}

// round 8
// speedup vs baseline: 1.7052x; 1.7052x over previous
#include <cuda_runtime.h>

#define Hc 2048
#define Wc 2048
#define UH 2049
#define UW 2048
#define VH 2048
#define VW 2049
#define DT 0.01f
#define VISC 0.001f

// Device scratch
__device__ float g_u  [UH * UW];
__device__ float g_v  [VH * VW];
__device__ float g_u2 [UH * UW];
__device__ float g_v2 [VH * VW];
__device__ float g_dens[Hc * Wc];
__device__ float g_div [Hc * Wc];
__device__ float g_p  [Hc * Wc];
__device__ float g_p2 [Hc * Wc];

__device__ __forceinline__ float bilerp(const float* __restrict__ f, int h, int w,
                                        float y, float x) {
    int x0 = (int)floorf(x);
    int x1 = x0 + 1;
    int y0 = (int)floorf(y);
    int y1 = y0 + 1;
    x0 = min(max(x0, 0), w - 1);
    x1 = min(max(x1, 0), w - 1);
    y0 = min(max(y0, 0), h - 1);
    y1 = min(max(y1, 0), h - 1);
    float x0f = (float)x0, x1f = (float)x1;
    float y0f = (float)y0, y1f = (float)y1;
    float wa = (x1f - x) * (y1f - y);
    float wb = (x - x0f) * (y1f - y);
    float wc = (x1f - x) * (y - y0f);
    float wd = (x - x0f) * (y - y0f);
    return wa * f[y0 * w + x0] + wb * f[y0 * w + x1]
         + wc * f[y1 * w + x0] + wd * f[y1 * w + x1];
}

// ================= fused diffuse (u | v+force | dens) =================
// blockIdx.z: 0 = u (2049x2048), 1 = v+force (2048x2049), 2 = dens (2048x2048)
__device__ __forceinline__ void diffuse_f4_body(const float* __restrict__ f,
                                                float* __restrict__ out,
                                                int h, int w, float a,
                                                int qx, int i) {
    int w4 = w >> 2;
    if (i >= h || qx >= w4) return;
    int j0 = qx * 4;
    const float4* f4 = (const float4*)f;
    float4 c  = f4[i * w4 + qx];
    int iu = max(i - 1, 0), id = min(i + 1, h - 1);
    float4 up = f4[iu * w4 + qx];
    float4 dn = f4[id * w4 + qx];
    float lf = (j0 > 0)       ? f[i * w + j0 - 1] : c.x;
    float rt = (j0 + 4 < w)   ? f[i * w + j0 + 4] : c.w;
    float4 r;
    r.x = c.x + a * (up.x + dn.x + lf  + c.y - 4.0f * c.x);
    r.y = c.y + a * (up.y + dn.y + c.x + c.z - 4.0f * c.y);
    r.z = c.z + a * (up.z + dn.z + c.y + c.w - 4.0f * c.z);
    r.w = c.w + a * (up.w + dn.w + c.z + rt  - 4.0f * c.w);
    ((float4*)out)[i * w4 + qx] = r;
}

// forced v value (scalar)
__device__ __forceinline__ float vfrc(const float* __restrict__ v,
                                      const float* __restrict__ dens,
                                      int i, int j) {
    float val = v[i * VW + j];
    if (j < Wc) val += (DT * 0.1f) * dens[i * Wc + j];
    return val;
}

// forced v "float4" at (i, j0..j0+3), j0+3 <= 2047. v loaded SCALAR (VW=2049
// stride -> odd rows are not 16B aligned); dens loaded float4 (Wc=2048 aligned).
__device__ __forceinline__ float4 vfrc4s(const float* __restrict__ v,
                                         const float* __restrict__ dens,
                                         int i, int j0) {
    const float* vr = &v[i * VW + j0];
    float4 val = make_float4(vr[0], vr[1], vr[2], vr[3]);
    float4 dd  = *(const float4*)&dens[i * Wc + j0];
    val.x += (DT * 0.1f) * dd.x;
    val.y += (DT * 0.1f) * dd.y;
    val.z += (DT * 0.1f) * dd.z;
    val.w += (DT * 0.1f) * dd.w;
    return val;
}

__global__ void diffuse_all_kernel(const float* __restrict__ u_in,
                                   const float* __restrict__ v_in,
                                   const float* __restrict__ dens_in,
                                   float* __restrict__ u_out,
                                   float* __restrict__ v_out,
                                   float* __restrict__ dens_out) {
    int qx = blockIdx.x * blockDim.x + threadIdx.x;
    int i  = blockIdx.y * blockDim.y + threadIdx.y;
    int z  = blockIdx.z;
    const float a  = DT * VISC;
    const float ad = DT * VISC * 0.1f;

    if (z == 0) {
        diffuse_f4_body(u_in, u_out, UH, UW, a, qx, i);
    } else if (z == 2) {
        diffuse_f4_body(dens_in, dens_out, Hc, Wc, ad, qx, i);
    } else {
        // v + force: cols [0,2048) in groups of 4 (scalar v loads), tail col 2048
        if (i >= VH || qx >= 512) return;
        int j0 = qx * 4;
        int iu = max(i - 1, 0), id = min(i + 1, VH - 1);
        float4 c  = vfrc4s(v_in, dens_in, i, j0);
        float4 up = vfrc4s(v_in, dens_in, iu, j0);
        float4 dn = vfrc4s(v_in, dens_in, id, j0);
        float lf = (j0 > 0) ? vfrc(v_in, dens_in, i, j0 - 1) : c.x;
        float rt = vfrc(v_in, dens_in, i, j0 + 4);   // j0+4 <= 2048 (col 2048 unforced)
        float4 r;
        r.x = c.x + a * (up.x + dn.x + lf  + c.y - 4.0f * c.x);
        r.y = c.y + a * (up.y + dn.y + c.x + c.z - 4.0f * c.y);
        r.z = c.z + a * (up.z + dn.z + c.y + c.w - 4.0f * c.z);
        r.w = c.w + a * (up.w + dn.w + c.z + rt  - 4.0f * c.w);
        float* vo = &v_out[i * VW + j0];
        vo[0] = r.x; vo[1] = r.y; vo[2] = r.z; vo[3] = r.w;
        if (qx == 511) {
            // tail column j = 2048 (never forced; rt clamps to itself)
            int j = 2048;
            float cc = v_in[i * VW + j];
            float u2 = v_in[iu * VW + j];
            float d2 = v_in[id * VW + j];
            float l2 = vfrc(v_in, dens_in, i, j - 1);
            v_out[i * VW + j] = cc + a * (u2 + d2 + l2 + cc - 4.0f * cc);
        }
    }
}

// ---- divergence ----
__global__ void div_f4_kernel(const float* __restrict__ u, const float* __restrict__ v,
                              float* __restrict__ dv) {
    int qx = blockIdx.x * blockDim.x + threadIdx.x;
    int i  = blockIdx.y * blockDim.y + threadIdx.y;
    int w4 = Wc >> 2;
    if (i >= Hc || qx >= w4) return;
    int j0 = qx * 4;
    const float4* u4 = (const float4*)u;
    float4 u0 = u4[i * w4 + qx];
    float4 u1 = u4[(i + 1) * w4 + qx];
    const float* vr = v + i * VW + j0;
    float v0 = vr[0], v1 = vr[1], v2 = vr[2], v3 = vr[3], v4 = vr[4];
    float4 r;
    r.x = (u1.x - u0.x + v1 - v0) / DT;
    r.y = (u1.y - u0.y + v2 - v1) / DT;
    r.z = (u1.z - u0.z + v3 - v2) / DT;
    r.w = (u1.w - u0.w + v4 - v3) / DT;
    ((float4*)dv)[i * w4 + qx] = r;
}

// ============ fused 4x Jacobi: register strips (2.5D) — R5 proven ============
#define OT 56

__device__ __forceinline__ float gload(const float* __restrict__ p, int gy, int gx) {
    return (gy >= 0 && gy < Hc && gx >= 0 && gx < Wc) ? p[gy * Wc + gx] : 0.0f;
}

__global__ void __launch_bounds__(128)
jacobiR_kernel(const float* __restrict__ pin, const float* __restrict__ dv,
               float* __restrict__ pout, int p_zero) {
    __shared__ float4 sTop[8][17];
    __shared__ float4 sBot[8][17];

    const int tx = threadIdx.x;              // 0..15
    const int ty = threadIdx.y;              // 0..7
    const int bx0 = blockIdx.x * OT - 4;
    const int by0 = blockIdx.y * OT - 4;
    const int gx0 = bx0 + tx * 4;
    const int gyBase = by0 + ty * 8;
    const bool border = (blockIdx.x == 0 || blockIdx.y == 0 ||
                         blockIdx.x == gridDim.x - 1 || blockIdx.y == gridDim.y - 1);

    float4 r[8], d[8];

    if (!border) {
        const float4* p4  = (const float4*)pin;
        const float4* dv4 = (const float4*)dv;
        int base = (gyBase * Wc + gx0) >> 2;
        const int rs = Wc >> 2;
        #pragma unroll
        for (int k = 0; k < 8; k++) {
            d[k] = dv4[base + k * rs];
        }
        if (p_zero) {
            float4 z = make_float4(0.f, 0.f, 0.f, 0.f);
            #pragma unroll
            for (int k = 0; k < 8; k++) r[k] = z;
        } else {
            #pragma unroll
            for (int k = 0; k < 8; k++) r[k] = p4[base + k * rs];
        }
    } else {
        #pragma unroll
        for (int k = 0; k < 8; k++) {
            int gy = gyBase + k;
            d[k] = make_float4(gload(dv, gy, gx0),     gload(dv, gy, gx0 + 1),
                               gload(dv, gy, gx0 + 2), gload(dv, gy, gx0 + 3));
            if (p_zero) r[k] = make_float4(0.f, 0.f, 0.f, 0.f);
            else        r[k] = make_float4(gload(pin, gy, gx0),     gload(pin, gy, gx0 + 1),
                                           gload(pin, gy, gx0 + 2), gload(pin, gy, gx0 + 3));
        }
    }

    bool rok[8];
    bool ok0 = (gx0     >= 1 && gx0     <= Wc - 2);
    bool ok1 = (gx0 + 1 >= 1 && gx0 + 1 <= Wc - 2);
    bool ok2 = (gx0 + 2 >= 1 && gx0 + 2 <= Wc - 2);
    bool ok3 = (gx0 + 3 >= 1 && gx0 + 3 <= Wc - 2);
    #pragma unroll
    for (int k = 0; k < 8; k++)
        rok[k] = (gyBase + k >= 1 && gyBase + k <= Hc - 2);

    const int tyUp = (ty == 0) ? 0 : ty - 1;
    const int tyDn = (ty == 7) ? 7 : ty + 1;

    #pragma unroll
    for (int t = 0; t < 4; t++) {
        sTop[ty][tx] = r[0];
        sBot[ty][tx] = r[7];
        __syncthreads();
        float4 up = sBot[tyUp][tx];
        float4 dn = sTop[tyDn][tx];
        __syncthreads();

        float4 prev = up;
        #pragma unroll
        for (int k = 0; k < 8; k++) {
            float4 ce = r[k];
            float4 below = (k == 7) ? dn : r[k + 1];
            float lf = __shfl_up_sync(0xffffffffu, ce.w, 1, 16);
            float rt = __shfl_down_sync(0xffffffffu, ce.x, 1, 16);
            float4 o;
            o.x = 0.25f * (prev.x + below.x + lf   + ce.y - d[k].x);
            o.y = 0.25f * (prev.y + below.y + ce.x + ce.z - d[k].y);
            o.z = 0.25f * (prev.z + below.z + ce.y + ce.w - d[k].z);
            o.w = 0.25f * (prev.w + below.w + ce.z + rt   - d[k].w);
            if (border) {
                o.x = (rok[k] && ok0) ? o.x : 0.f;
                o.y = (rok[k] && ok1) ? o.y : 0.f;
                o.z = (rok[k] && ok2) ? o.z : 0.f;
                o.w = (rok[k] && ok3) ? o.w : 0.f;
            }
            r[k] = o;
            prev = ce;
        }
    }

    if (tx >= 1 && tx < 15 && gx0 < Wc) {
        #pragma unroll
        for (int k = 0; k < 8; k++) {
            int trow = ty * 8 + k;
            if (trow >= 4 && trow < 60) {
                int gy = gyBase + k;
                if (gy < Hc)
                    *(float4*)&pout[gy * Wc + gx0] = r[k];
            }
        }
    }
}

// ---- pressure gradient ----
__global__ void grad_u_f4_kernel(float* __restrict__ u, const float* __restrict__ p) {
    int qx = blockIdx.x * blockDim.x + threadIdx.x;
    int i  = blockIdx.y * blockDim.y + threadIdx.y + 1;
    int w4 = Wc >> 2;
    if (i > UH - 2 || qx >= w4) return;
    const float4* p4 = (const float4*)p;
    float4 pc = p4[i * w4 + qx];
    float4 pm = p4[(i - 1) * w4 + qx];
    float4* u4 = (float4*)u;
    float4 uu = u4[i * w4 + qx];
    uu.x -= DT * (pc.x - pm.x);
    uu.y -= DT * (pc.y - pm.y);
    uu.z -= DT * (pc.z - pm.z);
    uu.w -= DT * (pc.w - pm.w);
    u4[i * w4 + qx] = uu;
}

__global__ void grad_v_kernel(float* __restrict__ v, const float* __restrict__ p) {
    int j = blockIdx.x * blockDim.x + threadIdx.x + 1;
    int i = blockIdx.y * blockDim.y + threadIdx.y;
    if (i >= VH || j > VW - 2) return;
    v[i * VW + j] -= DT * (p[i * Wc + j] - p[i * Wc + j - 1]);
}

// ---- advects ----
__global__ void advect_u_kernel(const float* __restrict__ u, const float* __restrict__ v,
                                float* __restrict__ out) {
    int j = blockIdx.x * blockDim.x + threadIdx.x;
    int i = blockIdx.y * blockDim.y + threadIdx.y;
    if (i >= UH || j >= UW) return;
    float Y = (float)i, X = (float)j;
    float x_u = fminf(fmaxf(X + 0.5f, 0.0f), (float)(UW - 1));
    float u_i = bilerp(u, UH, UW, Y, x_u);
    float y_v = fminf(fmaxf(Y + 0.5f, 0.0f), (float)(VH - 1));
    float v_i = bilerp(v, VH, VW, y_v, X);
    float px = fminf(fmaxf(X - DT * u_i, 0.0f), (float)(UW - 1));
    float py = fminf(fmaxf(Y - DT * v_i, 0.0f), (float)(UH - 1));
    out[i * UW + j] = bilerp(u, UH, UW, py, px);
}

__global__ void advect_v_kernel(const float* __restrict__ vold, const float* __restrict__ unew,
                                float* __restrict__ out) {
    int j = blockIdx.x * blockDim.x + threadIdx.x;
    int i = blockIdx.y * blockDim.y + threadIdx.y;
    if (i >= VH || j >= VW) return;
    float Y = (float)i, X = (float)j;
    float x_u = fminf(fmaxf(X + 0.5f, 0.0f), (float)(UW - 1));
    float u_i = bilerp(unew, UH, UW, Y, x_u);
    float y_v = fminf(fmaxf(Y + 0.5f, 0.0f), (float)(VH - 1));
    float v_i = bilerp(vold, VH, VW, y_v, X);
    float px = fminf(fmaxf(X - DT * u_i, 0.0f), (float)(VW - 1));
    float py = fminf(fmaxf(Y - DT * v_i, 0.0f), (float)(VH - 1));
    out[i * VW + j] = bilerp(vold, VH, VW, py, px);
}

__global__ void advect_dens_kernel(const float* __restrict__ dens,
                                   const float* __restrict__ unew,
                                   const float* __restrict__ vnew,
                                   float* __restrict__ out) {
    int j = blockIdx.x * blockDim.x + threadIdx.x;
    int i = blockIdx.y * blockDim.y + threadIdx.y;
    if (i >= Hc || j >= Wc) return;
    float Y = (float)i, X = (float)j;
    float x_u = fminf(fmaxf(X + 0.5f, 0.0f), (float)(UW - 1));
    float u_i = bilerp(unew, UH, UW, Y, x_u);
    float y_v = fminf(fmaxf(Y + 0.5f, 0.0f), (float)(VH - 1));
    float v_i = bilerp(vnew, VH, VW, y_v, X);
    float px = fminf(fmaxf(X - DT * u_i, 0.0f), (float)(Wc - 1));
    float py = fminf(fmaxf(Y - DT * v_i, 0.0f), (float)(Hc - 1));
    out[i * Wc + j] = 0.995f * bilerp(dens, Hc, Wc, py, px);
}

extern "C" void kernel_launch(void* const* d_in, const int* in_sizes, int n_in,
                              void* d_out, int out_size) {
    const float* u_in    = (const float*)d_in[0];
    const float* v_in    = (const float*)d_in[1];
    const float* dens_in = (const float*)d_in[2];
    float* out = (float*)d_out;

    float *du, *dv_, *du2, *dv2, *dd, *ddiv, *dp, *dp2;
    cudaGetSymbolAddress((void**)&du,   g_u);
    cudaGetSymbolAddress((void**)&dv_,  g_v);
    cudaGetSymbolAddress((void**)&du2,  g_u2);
    cudaGetSymbolAddress((void**)&dv2,  g_v2);
    cudaGetSymbolAddress((void**)&dd,   g_dens);
    cudaGetSymbolAddress((void**)&ddiv, g_div);
    cudaGetSymbolAddress((void**)&dp,   g_p);
    cudaGetSymbolAddress((void**)&dp2,  g_p2);

    int w4 = Wc >> 2;
    dim3 blkQ(64, 4);
    dim3 grdQ_S((w4 + 63) / 64, (Hc + 3) / 4);

    dim3 blkS(128, 2);
    dim3 grdV((VW + 127) / 128, (VH + 1) / 2);
    dim3 grdU((UW + 127) / 128, (UH + 1) / 2);
    dim3 grdS((Wc + 127) / 128, (Hc + 1) / 2);

    // 1. fused diffuse (u | v+force | dens) in one launch
    {
        dim3 grdD((w4 + 63) / 64, (UH + 3) / 4, 3);
        diffuse_all_kernel<<<grdD, blkQ>>>(u_in, v_in, dens_in, du, dv_, dd);
    }

    // 2. divergence
    div_f4_kernel<<<grdQ_S, blkQ>>>(du, dv_, ddiv);

    // 3. 20 Jacobi iterations = 5 fused x4 launches (register strips)
    {
        dim3 blkJ(16, 8);
        int gj = (Hc + OT - 1) / OT;   // 37
        dim3 grdJ(gj, gj);
        jacobiR_kernel<<<grdJ, blkJ>>>(dp2, ddiv, dp, 1);   // iters 1-4 (p0=0)
        jacobiR_kernel<<<grdJ, blkJ>>>(dp, ddiv, dp2, 0);   // 5-8
        jacobiR_kernel<<<grdJ, blkJ>>>(dp2, ddiv, dp, 0);   // 9-12
        jacobiR_kernel<<<grdJ, blkJ>>>(dp, ddiv, dp2, 0);   // 13-16
        jacobiR_kernel<<<grdJ, blkJ>>>(dp2, ddiv, dp, 0);   // 17-20 -> dp
    }

    // 4. projection
    {
        dim3 grdGU((w4 + 63) / 64, ((UH - 2) + 3) / 4);
        grad_u_f4_kernel<<<grdGU, blkQ>>>(du, dp);
        dim3 grdGV(((VW - 2) + 127) / 128, (VH + 1) / 2);
        grad_v_kernel<<<grdGV, blkS>>>(dv_, dp);
    }

    // 5. advect
    advect_u_kernel<<<grdU, blkS>>>(du, dv_, du2);
    advect_v_kernel<<<grdV, blkS>>>(dv_, du2, dv2);
    advect_dens_kernel<<<grdS, blkS>>>(dd, du2, dv2, out);
}

// round 9
// speedup vs baseline: 1.9632x; 1.1513x over previous
#include <cuda_runtime.h>

#define Hc 2048
#define Wc 2048
#define UH 2049
#define UW 2048
#define VH 2048
#define VW 2049
#define DT 0.01f
#define VISC 0.001f

// Device scratch
__device__ float g_u  [UH * UW];
__device__ float g_v  [VH * VW];
__device__ float g_u2 [UH * UW];
__device__ float g_v2 [VH * VW];
__device__ float g_dens[Hc * Wc];
__device__ float g_div [Hc * Wc];
__device__ float g_p  [Hc * Wc];
__device__ float g_p2 [Hc * Wc];

__device__ __forceinline__ float bilerp(const float* __restrict__ f, int h, int w,
                                        float y, float x) {
    int x0 = (int)floorf(x);
    int x1 = x0 + 1;
    int y0 = (int)floorf(y);
    int y1 = y0 + 1;
    x0 = min(max(x0, 0), w - 1);
    x1 = min(max(x1, 0), w - 1);
    y0 = min(max(y0, 0), h - 1);
    y1 = min(max(y1, 0), h - 1);
    float x0f = (float)x0, x1f = (float)x1;
    float y0f = (float)y0, y1f = (float)y1;
    float wa = (x1f - x) * (y1f - y);
    float wb = (x - x0f) * (y1f - y);
    float wc = (x1f - x) * (y - y0f);
    float wd = (x - x0f) * (y - y0f);
    return wa * f[y0 * w + x0] + wb * f[y0 * w + x1]
         + wc * f[y1 * w + x0] + wd * f[y1 * w + x1];
}

// ================= fused diffuse (u | v+force | dens) =================
__device__ __forceinline__ void diffuse_f4_body(const float* __restrict__ f,
                                                float* __restrict__ out,
                                                int h, int w, float a,
                                                int qx, int i) {
    int w4 = w >> 2;
    if (i >= h || qx >= w4) return;
    int j0 = qx * 4;
    const float4* f4 = (const float4*)f;
    float4 c  = f4[i * w4 + qx];
    int iu = max(i - 1, 0), id = min(i + 1, h - 1);
    float4 up = f4[iu * w4 + qx];
    float4 dn = f4[id * w4 + qx];
    float lf = (j0 > 0)       ? f[i * w + j0 - 1] : c.x;
    float rt = (j0 + 4 < w)   ? f[i * w + j0 + 4] : c.w;
    float4 r;
    r.x = c.x + a * (up.x + dn.x + lf  + c.y - 4.0f * c.x);
    r.y = c.y + a * (up.y + dn.y + c.x + c.z - 4.0f * c.y);
    r.z = c.z + a * (up.z + dn.z + c.y + c.w - 4.0f * c.z);
    r.w = c.w + a * (up.w + dn.w + c.z + rt  - 4.0f * c.w);
    ((float4*)out)[i * w4 + qx] = r;
}

__device__ __forceinline__ float vfrc(const float* __restrict__ v,
                                      const float* __restrict__ dens,
                                      int i, int j) {
    float val = v[i * VW + j];
    if (j < Wc) val += (DT * 0.1f) * dens[i * Wc + j];
    return val;
}

__device__ __forceinline__ float4 vfrc4s(const float* __restrict__ v,
                                         const float* __restrict__ dens,
                                         int i, int j0) {
    const float* vr = &v[i * VW + j0];
    float4 val = make_float4(vr[0], vr[1], vr[2], vr[3]);
    float4 dd  = *(const float4*)&dens[i * Wc + j0];
    val.x += (DT * 0.1f) * dd.x;
    val.y += (DT * 0.1f) * dd.y;
    val.z += (DT * 0.1f) * dd.z;
    val.w += (DT * 0.1f) * dd.w;
    return val;
}

__global__ void diffuse_all_kernel(const float* __restrict__ u_in,
                                   const float* __restrict__ v_in,
                                   const float* __restrict__ dens_in,
                                   float* __restrict__ u_out,
                                   float* __restrict__ v_out,
                                   float* __restrict__ dens_out) {
    int qx = blockIdx.x * blockDim.x + threadIdx.x;
    int i  = blockIdx.y * blockDim.y + threadIdx.y;
    int z  = blockIdx.z;
    const float a  = DT * VISC;
    const float ad = DT * VISC * 0.1f;

    if (z == 0) {
        diffuse_f4_body(u_in, u_out, UH, UW, a, qx, i);
    } else if (z == 2) {
        diffuse_f4_body(dens_in, dens_out, Hc, Wc, ad, qx, i);
    } else {
        if (i >= VH || qx >= 512) return;
        int j0 = qx * 4;
        int iu = max(i - 1, 0), id = min(i + 1, VH - 1);
        float4 c  = vfrc4s(v_in, dens_in, i, j0);
        float4 up = vfrc4s(v_in, dens_in, iu, j0);
        float4 dn = vfrc4s(v_in, dens_in, id, j0);
        float lf = (j0 > 0) ? vfrc(v_in, dens_in, i, j0 - 1) : c.x;
        float rt = vfrc(v_in, dens_in, i, j0 + 4);
        float4 r;
        r.x = c.x + a * (up.x + dn.x + lf  + c.y - 4.0f * c.x);
        r.y = c.y + a * (up.y + dn.y + c.x + c.z - 4.0f * c.y);
        r.z = c.z + a * (up.z + dn.z + c.y + c.w - 4.0f * c.z);
        r.w = c.w + a * (up.w + dn.w + c.z + rt  - 4.0f * c.w);
        float* vo = &v_out[i * VW + j0];
        vo[0] = r.x; vo[1] = r.y; vo[2] = r.z; vo[3] = r.w;
        if (qx == 511) {
            int j = 2048;
            float cc = v_in[i * VW + j];
            float u2 = v_in[iu * VW + j];
            float d2 = v_in[id * VW + j];
            float l2 = vfrc(v_in, dens_in, i, j - 1);
            v_out[i * VW + j] = cc + a * (u2 + d2 + l2 + cc - 4.0f * cc);
        }
    }
}

// ---- divergence ----
__global__ void div_f4_kernel(const float* __restrict__ u, const float* __restrict__ v,
                              float* __restrict__ dv) {
    int qx = blockIdx.x * blockDim.x + threadIdx.x;
    int i  = blockIdx.y * blockDim.y + threadIdx.y;
    int w4 = Wc >> 2;
    if (i >= Hc || qx >= w4) return;
    int j0 = qx * 4;
    const float4* u4 = (const float4*)u;
    float4 u0 = u4[i * w4 + qx];
    float4 u1 = u4[(i + 1) * w4 + qx];
    const float* vr = v + i * VW + j0;
    float v0 = vr[0], v1 = vr[1], v2 = vr[2], v3 = vr[3], v4 = vr[4];
    float4 r;
    r.x = (u1.x - u0.x + v1 - v0) / DT;
    r.y = (u1.y - u0.y + v2 - v1) / DT;
    r.z = (u1.z - u0.z + v3 - v2) / DT;
    r.w = (u1.w - u0.w + v4 - v3) / DT;
    ((float4*)dv)[i * w4 + qx] = r;
}

// ============ fused 4x Jacobi: 4-row register strips, block (16,16) ============
#define OT 56

__device__ __forceinline__ float gload(const float* __restrict__ p, int gy, int gx) {
    return (gy >= 0 && gy < Hc && gx >= 0 && gx < Wc) ? p[gy * Wc + gx] : 0.0f;
}

__global__ void __launch_bounds__(256)
jacobiR_kernel(const float* __restrict__ pin, const float* __restrict__ dv,
               float* __restrict__ pout, int p_zero) {
    __shared__ float4 sTop[16][17];
    __shared__ float4 sBot[16][17];

    const int tx = threadIdx.x;              // 0..15
    const int ty = threadIdx.y;              // 0..15
    const int bx0 = blockIdx.x * OT - 4;
    const int by0 = blockIdx.y * OT - 4;
    const int gx0 = bx0 + tx * 4;
    const int gyBase = by0 + ty * 4;
    const bool border = (blockIdx.x == 0 || blockIdx.y == 0 ||
                         blockIdx.x == gridDim.x - 1 || blockIdx.y == gridDim.y - 1);

    float4 r[4], d[4];

    if (!border) {
        const float4* p4  = (const float4*)pin;
        const float4* dv4 = (const float4*)dv;
        int base = (gyBase * Wc + gx0) >> 2;
        const int rs = Wc >> 2;
        #pragma unroll
        for (int k = 0; k < 4; k++) d[k] = dv4[base + k * rs];
        if (p_zero) {
            float4 z = make_float4(0.f, 0.f, 0.f, 0.f);
            #pragma unroll
            for (int k = 0; k < 4; k++) r[k] = z;
        } else {
            #pragma unroll
            for (int k = 0; k < 4; k++) r[k] = p4[base + k * rs];
        }
    } else {
        #pragma unroll
        for (int k = 0; k < 4; k++) {
            int gy = gyBase + k;
            d[k] = make_float4(gload(dv, gy, gx0),     gload(dv, gy, gx0 + 1),
                               gload(dv, gy, gx0 + 2), gload(dv, gy, gx0 + 3));
            if (p_zero) r[k] = make_float4(0.f, 0.f, 0.f, 0.f);
            else        r[k] = make_float4(gload(pin, gy, gx0),     gload(pin, gy, gx0 + 1),
                                           gload(pin, gy, gx0 + 2), gload(pin, gy, gx0 + 3));
        }
    }

    bool rok[4];
    bool ok0 = (gx0     >= 1 && gx0     <= Wc - 2);
    bool ok1 = (gx0 + 1 >= 1 && gx0 + 1 <= Wc - 2);
    bool ok2 = (gx0 + 2 >= 1 && gx0 + 2 <= Wc - 2);
    bool ok3 = (gx0 + 3 >= 1 && gx0 + 3 <= Wc - 2);
    #pragma unroll
    for (int k = 0; k < 4; k++)
        rok[k] = (gyBase + k >= 1 && gyBase + k <= Hc - 2);

    const int tyUp = (ty == 0)  ? 0  : ty - 1;
    const int tyDn = (ty == 15) ? 15 : ty + 1;

    #pragma unroll
    for (int t = 0; t < 4; t++) {
        sTop[ty][tx] = r[0];
        sBot[ty][tx] = r[3];
        __syncthreads();
        float4 up = sBot[tyUp][tx];
        float4 dn = sTop[tyDn][tx];
        __syncthreads();

        float4 prev = up;
        #pragma unroll
        for (int k = 0; k < 4; k++) {
            float4 ce = r[k];
            float4 below = (k == 3) ? dn : r[k + 1];
            float lf = __shfl_up_sync(0xffffffffu, ce.w, 1, 16);
            float rt = __shfl_down_sync(0xffffffffu, ce.x, 1, 16);
            float4 o;
            o.x = 0.25f * (prev.x + below.x + lf   + ce.y - d[k].x);
            o.y = 0.25f * (prev.y + below.y + ce.x + ce.z - d[k].y);
            o.z = 0.25f * (prev.z + below.z + ce.y + ce.w - d[k].z);
            o.w = 0.25f * (prev.w + below.w + ce.z + rt   - d[k].w);
            if (border) {
                o.x = (rok[k] && ok0) ? o.x : 0.f;
                o.y = (rok[k] && ok1) ? o.y : 0.f;
                o.z = (rok[k] && ok2) ? o.z : 0.f;
                o.w = (rok[k] && ok3) ? o.w : 0.f;
            }
            r[k] = o;
            prev = ce;
        }
    }

    if (tx >= 1 && tx < 15 && gx0 < Wc) {
        #pragma unroll
        for (int k = 0; k < 4; k++) {
            int trow = ty * 4 + k;
            if (trow >= 4 && trow < 60) {
                int gy = gyBase + k;
                if (gy < Hc)
                    *(float4*)&pout[gy * Wc + gx0] = r[k];
            }
        }
    }
}

// ---- fused pressure gradient (z=0: u float4, z=1: v scalar) ----
__global__ void grad_all_kernel(float* __restrict__ u, float* __restrict__ v,
                                const float* __restrict__ p) {
    int w4 = Wc >> 2;
    if (blockIdx.z == 0) {
        int qx = blockIdx.x * blockDim.x + threadIdx.x;
        int i  = blockIdx.y * blockDim.y + threadIdx.y + 1;
        if (i > UH - 2 || qx >= w4) return;
        const float4* p4 = (const float4*)p;
        float4 pc = p4[i * w4 + qx];
        float4 pm = p4[(i - 1) * w4 + qx];
        float4* u4 = (float4*)u;
        float4 uu = u4[i * w4 + qx];
        uu.x -= DT * (pc.x - pm.x);
        uu.y -= DT * (pc.y - pm.y);
        uu.z -= DT * (pc.z - pm.z);
        uu.w -= DT * (pc.w - pm.w);
        u4[i * w4 + qx] = uu;
    } else {
        // v cols 1..2047, 4 per thread (scalar ld/st, odd stride)
        int qx = blockIdx.x * blockDim.x + threadIdx.x;
        int i  = blockIdx.y * blockDim.y + threadIdx.y;
        if (i >= VH || qx >= w4) return;
        int j0 = qx * 4;   // handle cols j0+1 .. j0+4 (1..2048 range), skip 2048
        const float* pr = &p[i * Wc];
        float* vr = &v[i * VW];
        #pragma unroll
        for (int e = 1; e <= 4; e++) {
            int j = j0 + e;
            if (j <= VW - 2)
                vr[j] -= DT * (pr[j] - pr[j - 1]);
        }
    }
}

// ---- advects (simplified velocity sampling: exact half-offset averages) ----
__global__ void advect_u_kernel(const float* __restrict__ u, const float* __restrict__ v,
                                float* __restrict__ out) {
    int j = blockIdx.x * blockDim.x + threadIdx.x;
    int i = blockIdx.y * blockDim.y + threadIdx.y;
    if (i >= UH || j >= UW) return;
    float Y = (float)i, X = (float)j;
    // u_i = bilerp(u, Y, clip(X+0.5)): exact -> 0.5*(u[i][j]+u[i][j+1]), 0 at j=UW-1
    float u_i = (j < UW - 1) ? 0.5f * (u[i * UW + j] + u[i * UW + j + 1]) : 0.0f;
    // v_i = bilerp(v, clip(Y+0.5), X): exact -> 0.5*(v[i][j]+v[i+1][j]), 0 for i>=VH-1
    float v_i = (i < VH - 1) ? 0.5f * (v[i * VW + j] + v[(i + 1) * VW + j]) : 0.0f;
    float px = fminf(fmaxf(X - DT * u_i, 0.0f), (float)(UW - 1));
    float py = fminf(fmaxf(Y - DT * v_i, 0.0f), (float)(UH - 1));
    out[i * UW + j] = bilerp(u, UH, UW, py, px);
}

__global__ void advect_v_kernel(const float* __restrict__ vold, const float* __restrict__ unew,
                                float* __restrict__ out) {
    int j = blockIdx.x * blockDim.x + threadIdx.x;
    int i = blockIdx.y * blockDim.y + threadIdx.y;
    if (i >= VH || j >= VW) return;
    float Y = (float)i, X = (float)j;
    // u_i: 0.5*(unew[i][j]+unew[i][j+1]) for j < UW-1; 0 for j >= 2047
    float u_i = (j < UW - 1) ? 0.5f * (unew[i * UW + j] + unew[i * UW + j + 1]) : 0.0f;
    // v_i: 0.5*(vold[i][j]+vold[i+1][j]) for i < VH-1; 0 at i=2047
    float v_i = (i < VH - 1) ? 0.5f * (vold[i * VW + j] + vold[(i + 1) * VW + j]) : 0.0f;
    float px = fminf(fmaxf(X - DT * u_i, 0.0f), (float)(VW - 1));
    float py = fminf(fmaxf(Y - DT * v_i, 0.0f), (float)(VH - 1));
    out[i * VW + j] = bilerp(vold, VH, VW, py, px);
}

__global__ void advect_dens_kernel(const float* __restrict__ dens,
                                   const float* __restrict__ unew,
                                   const float* __restrict__ vnew,
                                   float* __restrict__ out) {
    int j = blockIdx.x * blockDim.x + threadIdx.x;
    int i = blockIdx.y * blockDim.y + threadIdx.y;
    if (i >= Hc || j >= Wc) return;
    float Y = (float)i, X = (float)j;
    float u_i = (j < UW - 1) ? 0.5f * (unew[i * UW + j] + unew[i * UW + j + 1]) : 0.0f;
    float v_i = (i < VH - 1) ? 0.5f * (vnew[i * VW + j] + vnew[(i + 1) * VW + j]) : 0.0f;
    float px = fminf(fmaxf(X - DT * u_i, 0.0f), (float)(Wc - 1));
    float py = fminf(fmaxf(Y - DT * v_i, 0.0f), (float)(Hc - 1));
    out[i * Wc + j] = 0.995f * bilerp(dens, Hc, Wc, py, px);
}

extern "C" void kernel_launch(void* const* d_in, const int* in_sizes, int n_in,
                              void* d_out, int out_size) {
    const float* u_in    = (const float*)d_in[0];
    const float* v_in    = (const float*)d_in[1];
    const float* dens_in = (const float*)d_in[2];
    float* out = (float*)d_out;

    float *du, *dv_, *du2, *dv2, *dd, *ddiv, *dp, *dp2;
    cudaGetSymbolAddress((void**)&du,   g_u);
    cudaGetSymbolAddress((void**)&dv_,  g_v);
    cudaGetSymbolAddress((void**)&du2,  g_u2);
    cudaGetSymbolAddress((void**)&dv2,  g_v2);
    cudaGetSymbolAddress((void**)&dd,   g_dens);
    cudaGetSymbolAddress((void**)&ddiv, g_div);
    cudaGetSymbolAddress((void**)&dp,   g_p);
    cudaGetSymbolAddress((void**)&dp2,  g_p2);

    int w4 = Wc >> 2;
    dim3 blkQ(64, 4);
    dim3 grdQ_S((w4 + 63) / 64, (Hc + 3) / 4);

    dim3 blkS(128, 2);
    dim3 grdV((VW + 127) / 128, (VH + 1) / 2);
    dim3 grdU((UW + 127) / 128, (UH + 1) / 2);
    dim3 grdS((Wc + 127) / 128, (Hc + 1) / 2);

    // 1. fused diffuse
    {
        dim3 grdD((w4 + 63) / 64, (UH + 3) / 4, 3);
        diffuse_all_kernel<<<grdD, blkQ>>>(u_in, v_in, dens_in, du, dv_, dd);
    }

    // 2. divergence
    div_f4_kernel<<<grdQ_S, blkQ>>>(du, dv_, ddiv);

    // 3. 20 Jacobi iterations = 5 fused x4 launches
    {
        dim3 blkJ(16, 16);
        int gj = (Hc + OT - 1) / OT;   // 37
        dim3 grdJ(gj, gj);
        jacobiR_kernel<<<grdJ, blkJ>>>(dp2, ddiv, dp, 1);
        jacobiR_kernel<<<grdJ, blkJ>>>(dp, ddiv, dp2, 0);
        jacobiR_kernel<<<grdJ, blkJ>>>(dp2, ddiv, dp, 0);
        jacobiR_kernel<<<grdJ, blkJ>>>(dp, ddiv, dp2, 0);
        jacobiR_kernel<<<grdJ, blkJ>>>(dp2, ddiv, dp, 0);   // -> dp
    }

    // 4. fused projection
    {
        dim3 grdG((w4 + 63) / 64, (UH + 3) / 4, 2);
        grad_all_kernel<<<grdG, blkQ>>>(du, dv_, dp);
    }

    // 5. advect
    advect_u_kernel<<<grdU, blkS>>>(du, dv_, du2);
    advect_v_kernel<<<grdV, blkS>>>(dv_, du2, dv2);
    advect_dens_kernel<<<grdS, blkS>>>(dd, du2, dv2, out);
}